// round 10
// baseline (speedup 1.0000x reference)
#include <cuda_runtime.h>
#include <cuda_bf16.h>
#include <cuda_fp16.h>

#define K_NB    10
#define K_TOT   300
#define TPB     256
#define BLKS_PER_SM 4
#define NUM_SMS 148

// Fused fp16 table, 16B per control point (one LDS.128 per gather):
//  sqb[j] = { h2(qw,qx), h2(qy,qz), h2(b0,b1), h2(b2,0) }
// q normalized in fp32; b = p + t - rot_q(p). Blend arithmetic fp32.

__device__ __forceinline__ void quat_rotate(float cw, float cx, float cy, float cz,
                                            float vx, float vy, float vz,
                                            float& ox, float& oy, float& oz)
{
    float tx = cy * vz - cz * vy;
    float ty = cz * vx - cx * vz;
    float tz = cx * vy - cy * vx;
    float ux = cy * tz - cz * ty;
    float uy = cz * tx - cx * tz;
    float uz = cx * ty - cy * tx;
    ox = fmaf(2.f, fmaf(cw, tx, ux), vx);
    oy = fmaf(2.f, fmaf(cw, ty, uy), vy);
    oz = fmaf(2.f, fmaf(cw, tz, uz), vz);
}

__device__ __forceinline__ unsigned int pack_h2(float a, float b)
{
    __half2 h = __floats2half2_rn(a, b);
    return *reinterpret_cast<unsigned int*>(&h);
}

__device__ __forceinline__ void load_inputs(const float* __restrict__ means,
                                            const float* __restrict__ weights,
                                            const int*   __restrict__ indices,
                                            int i,
                                            float& mx, float& my, float& mz,
                                            float2* wv, int2* jv)
{
    mx = means[i * 3 + 0];
    my = means[i * 3 + 1];
    mz = means[i * 3 + 2];
    const float2* wp = reinterpret_cast<const float2*>(weights + (size_t)i * K_NB);
    const int2*   ip = reinterpret_cast<const int2*>(indices + (size_t)i * K_NB);
    #pragma unroll
    for (int c = 0; c < K_NB / 2; c++) {
        wv[c] = wp[c];
        jv[c] = ip[c];
    }
}

__global__ __launch_bounds__(TPB, BLKS_PER_SM)
void deform4d_kernel(const float* __restrict__ means,
                     const float* __restrict__ quats,
                     const float* __restrict__ weights,
                     const float* __restrict__ ctrl_trans,
                     const float* __restrict__ ctrl_rots,
                     const float* __restrict__ ctrl_pos,
                     const int*   __restrict__ indices,
                     float* __restrict__ out_means,
                     float* __restrict__ out_quats,
                     int n)
{
    __shared__ uint4 sqb[K_TOT];   // 4.8 KB fused fp16 table

    // ---- build fused control-point table once per (persistent) block ----
    for (int j = threadIdx.x; j < K_TOT; j += TPB) {
        float4 q = reinterpret_cast<const float4*>(ctrl_rots)[j];
        float nrm = sqrtf(q.x * q.x + q.y * q.y + q.z * q.z + q.w * q.w);
        float inv = 1.0f / fmaxf(nrm, 1e-8f);
        float cw = q.x * inv, cx = q.y * inv, cy = q.z * inv, cz = q.w * inv;

        float px = ctrl_pos[j * 3 + 0];
        float py = ctrl_pos[j * 3 + 1];
        float pz = ctrl_pos[j * 3 + 2];

        float rpx, rpy, rpz;
        quat_rotate(cw, cx, cy, cz, px, py, pz, rpx, rpy, rpz);

        float b0 = px + ctrl_trans[j * 3 + 0] - rpx;
        float b1 = py + ctrl_trans[j * 3 + 1] - rpy;
        float b2 = pz + ctrl_trans[j * 3 + 2] - rpz;

        uint4 e;
        e.x = pack_h2(cw, cx);
        e.y = pack_h2(cy, cz);
        e.z = pack_h2(b0, b1);
        e.w = pack_h2(b2, 0.f);
        sqb[j] = e;
    }
    __syncthreads();

    const int stride = gridDim.x * TPB;

    int i = blockIdx.x * TPB + threadIdx.x;
    if (i >= n) return;

    // ---- current-iteration buffers (prefetched) ----
    float  mx, my, mz;
    float2 wv[K_NB / 2];
    int2   jv[K_NB / 2];
    load_inputs(means, weights, indices, i, mx, my, mz, wv, jv);

    while (true) {
        const int inext = i + stride;
        const bool hasnext = (inext < n);

        // ---- prefetch next iteration's inputs (issues LDGs ~2000 cyc early) ----
        float  nmx = 0.f, nmy = 0.f, nmz = 0.f;
        float2 nwv[K_NB / 2];
        int2   njv[K_NB / 2];
        if (hasnext) {
            load_inputs(means, weights, indices, inext, nmx, nmy, nmz, nwv, njv);
        }

        // ---- blend current gaussian ----
        float am0 = 0.f, am1 = 0.f, am2 = 0.f;
        float aq0 = 0.f, aq1 = 0.f, aq2 = 0.f, aq3 = 0.f;

        #pragma unroll
        for (int c = 0; c < K_NB / 2; c++) {
            float2 tw = wv[c];
            int2   ti = jv[c];

            #pragma unroll
            for (int h = 0; h < 2; h++) {
                const float w = (h == 0) ? tw.x : tw.y;
                const int   j = (h == 0) ? ti.x : ti.y;

                uint4 e = sqb[j];
                float2 qwx = __half22float2(*reinterpret_cast<__half2*>(&e.x));
                float2 qyz = __half22float2(*reinterpret_cast<__half2*>(&e.y));
                float2 b01 = __half22float2(*reinterpret_cast<__half2*>(&e.z));
                float  b2  = __low2float(*reinterpret_cast<__half2*>(&e.w));

                float vx, vy, vz;
                quat_rotate(qwx.x, qwx.y, qyz.x, qyz.y, mx, my, mz, vx, vy, vz);

                am0 = fmaf(w, vx + b01.x, am0);
                am1 = fmaf(w, vy + b01.y, am1);
                am2 = fmaf(w, vz + b2,    am2);

                aq0 = fmaf(w, qwx.x, aq0);
                aq1 = fmaf(w, qwx.y, aq1);
                aq2 = fmaf(w, qyz.x, aq2);
                aq3 = fmaf(w, qyz.y, aq3);
            }
        }

        float4 gq = reinterpret_cast<const float4*>(quats)[i];   // (w,x,y,z)

        float nrm = sqrtf(aq0 * aq0 + aq1 * aq1 + aq2 * aq2 + aq3 * aq3);
        float inv = 1.0f / fmaxf(nrm, 1e-8f);
        float aw = aq0 * inv, ax = aq1 * inv, ay = aq2 * inv, az = aq3 * inv;

        float bw = gq.x, bx = gq.y, by = gq.z, bz = gq.w;
        float4 qo;
        qo.x = aw * bw - ax * bx - ay * by - az * bz;
        qo.y = aw * bx + ax * bw + ay * bz - az * by;
        qo.z = aw * by - ax * bz + ay * bw + az * bx;
        qo.w = aw * bz + ax * by - ay * bx + az * bw;

        out_means[i * 3 + 0] = am0;
        out_means[i * 3 + 1] = am1;
        out_means[i * 3 + 2] = am2;
        reinterpret_cast<float4*>(out_quats)[i] = qo;

        if (!hasnext) break;

        // ---- rotate buffers ----
        i = inext;
        mx = nmx; my = nmy; mz = nmz;
        #pragma unroll
        for (int c = 0; c < K_NB / 2; c++) {
            wv[c] = nwv[c];
            jv[c] = njv[c];
        }
    }
}

extern "C" void kernel_launch(void* const* d_in, const int* in_sizes, int n_in,
                              void* d_out, int out_size)
{
    const float* means      = (const float*)d_in[0];
    const float* quats      = (const float*)d_in[1];
    const float* weights    = (const float*)d_in[2];
    const float* ctrl_trans = (const float*)d_in[3];
    const float* ctrl_rots  = (const float*)d_in[4];
    const float* ctrl_pos   = (const float*)d_in[5];
    const int*   indices    = (const int*)d_in[6];

    int n = in_sizes[0] / 3;  // means is [N,3]

    float* out_means = (float*)d_out;
    float* out_quats = (float*)d_out + (size_t)n * 3;

    int max_blocks = NUM_SMS * BLKS_PER_SM;
    int need = (n + TPB - 1) / TPB;
    int blocks = need < max_blocks ? need : max_blocks;

    deform4d_kernel<<<blocks, TPB>>>(means, quats, weights,
                                     ctrl_trans, ctrl_rots, ctrl_pos,
                                     indices, out_means, out_quats, n);
}

// round 11
// speedup vs baseline: 1.0198x; 1.0198x over previous
#include <cuda_runtime.h>
#include <cuda_bf16.h>
#include <cuda_fp16.h>

#define K_NB    10
#define K_TOT   300
#define TPB     256
#define BLKS_PER_SM 6
#define NUM_SMS 148

// Fused fp16 table, 16B per control point (one LDS.128 per gather):
//  sqb[j] = { h2(qw,qx), h2(qy,qz), h2(b0,b1), h2(b2,delta) }
// q normalized in fp32; b = p + t - rot_q(p); delta = qw^2 - |qv|^2.
// Blend uses the linear decomposition:
//   sum_k w rot(m) + w b = L*m + 2P + 2(G x m) + B
//   L = sum w*delta, P = sum w*(qv.m)*qv, G = sum w*qw*qv, B = sum w*b

__device__ __forceinline__ void quat_rotate(float cw, float cx, float cy, float cz,
                                            float vx, float vy, float vz,
                                            float& ox, float& oy, float& oz)
{
    float tx = cy * vz - cz * vy;
    float ty = cz * vx - cx * vz;
    float tz = cx * vy - cy * vx;
    float ux = cy * tz - cz * ty;
    float uy = cz * tx - cx * tz;
    float uz = cx * ty - cy * tx;
    ox = fmaf(2.f, fmaf(cw, tx, ux), vx);
    oy = fmaf(2.f, fmaf(cw, ty, uy), vy);
    oz = fmaf(2.f, fmaf(cw, tz, uz), vz);
}

__device__ __forceinline__ unsigned int pack_h2(float a, float b)
{
    __half2 h = __floats2half2_rn(a, b);
    return *reinterpret_cast<unsigned int*>(&h);
}

__global__ __launch_bounds__(TPB, BLKS_PER_SM)
void deform4d_kernel(const float* __restrict__ means,
                     const float* __restrict__ quats,
                     const float* __restrict__ weights,
                     const float* __restrict__ ctrl_trans,
                     const float* __restrict__ ctrl_rots,
                     const float* __restrict__ ctrl_pos,
                     const int*   __restrict__ indices,
                     float* __restrict__ out_means,
                     float* __restrict__ out_quats,
                     int n)
{
    __shared__ uint4 sqb[K_TOT];   // 4.8 KB fused fp16 table

    // ---- build fused control-point table once per (persistent) block ----
    for (int j = threadIdx.x; j < K_TOT; j += TPB) {
        float4 q = reinterpret_cast<const float4*>(ctrl_rots)[j];
        float nrm = sqrtf(q.x * q.x + q.y * q.y + q.z * q.z + q.w * q.w);
        float inv = 1.0f / fmaxf(nrm, 1e-8f);
        float cw = q.x * inv, cx = q.y * inv, cy = q.z * inv, cz = q.w * inv;

        float px = ctrl_pos[j * 3 + 0];
        float py = ctrl_pos[j * 3 + 1];
        float pz = ctrl_pos[j * 3 + 2];

        float rpx, rpy, rpz;
        quat_rotate(cw, cx, cy, cz, px, py, pz, rpx, rpy, rpz);

        float b0 = px + ctrl_trans[j * 3 + 0] - rpx;
        float b1 = py + ctrl_trans[j * 3 + 1] - rpy;
        float b2 = pz + ctrl_trans[j * 3 + 2] - rpz;

        float delta = cw * cw - (cx * cx + cy * cy + cz * cz);

        uint4 e;
        e.x = pack_h2(cw, cx);
        e.y = pack_h2(cy, cz);
        e.z = pack_h2(b0, b1);
        e.w = pack_h2(b2, delta);
        sqb[j] = e;
    }
    __syncthreads();

    const int stride = gridDim.x * TPB;

    for (int i = blockIdx.x * TPB + threadIdx.x; i < n; i += stride) {
        float mx = means[i * 3 + 0];
        float my = means[i * 3 + 1];
        float mz = means[i * 3 + 2];

        const float2* wp = reinterpret_cast<const float2*>(weights + (size_t)i * K_NB);
        const int2*   ip = reinterpret_cast<const int2*>(indices + (size_t)i * K_NB);

        float P0 = 0.f, P1 = 0.f, P2 = 0.f;      // sum w (qv.m) qv
        float G0 = 0.f, G1 = 0.f, G2 = 0.f;      // sum w qw qv
        float B0 = 0.f, B1 = 0.f, B2 = 0.f;      // sum w b
        float L  = 0.f;                           // sum w delta
        float aq0 = 0.f, aq1 = 0.f, aq2 = 0.f, aq3 = 0.f;  // sum w q

        #pragma unroll
        for (int c = 0; c < K_NB / 2; c++) {
            float2 tw = wp[c];
            int2   ti = ip[c];

            #pragma unroll
            for (int h = 0; h < 2; h++) {
                const float w = (h == 0) ? tw.x : tw.y;
                const int   j = (h == 0) ? ti.x : ti.y;

                uint4 e = sqb[j];
                float2 qwx = __half22float2(*reinterpret_cast<__half2*>(&e.x));
                float2 qyz = __half22float2(*reinterpret_cast<__half2*>(&e.y));
                float2 b01 = __half22float2(*reinterpret_cast<__half2*>(&e.z));
                float2 b2d = __half22float2(*reinterpret_cast<__half2*>(&e.w));

                const float qw = qwx.x, qx = qwx.y, qy = qyz.x, qz = qyz.y;

                float d  = fmaf(qz, mz, fmaf(qy, my, qx * mx));
                float wd = w * d;
                P0 = fmaf(wd, qx, P0);
                P1 = fmaf(wd, qy, P1);
                P2 = fmaf(wd, qz, P2);

                float wqw = w * qw;
                aq0 += wqw;
                G0 = fmaf(wqw, qx, G0);
                G1 = fmaf(wqw, qy, G1);
                G2 = fmaf(wqw, qz, G2);

                aq1 = fmaf(w, qx, aq1);
                aq2 = fmaf(w, qy, aq2);
                aq3 = fmaf(w, qz, aq3);

                L  = fmaf(w, b2d.y, L);
                B0 = fmaf(w, b01.x, B0);
                B1 = fmaf(w, b01.y, B1);
                B2 = fmaf(w, b2d.x, B2);
            }
        }

        // ---- reconstruct blended mean: L*m + 2P + 2(G x m) + B ----
        float cx = G1 * mz - G2 * my;
        float cy = G2 * mx - G0 * mz;
        float cz = G0 * my - G1 * mx;

        float am0 = fmaf(L, mx, fmaf(2.f, P0 + cx, B0));
        float am1 = fmaf(L, my, fmaf(2.f, P1 + cy, B1));
        float am2 = fmaf(L, mz, fmaf(2.f, P2 + cz, B2));

        float4 gq = reinterpret_cast<const float4*>(quats)[i];   // (w,x,y,z)

        float nrm = sqrtf(aq0 * aq0 + aq1 * aq1 + aq2 * aq2 + aq3 * aq3);
        float inv = 1.0f / fmaxf(nrm, 1e-8f);
        float aw = aq0 * inv, ax = aq1 * inv, ay = aq2 * inv, az = aq3 * inv;

        float bw = gq.x, bx = gq.y, by = gq.z, bz = gq.w;
        float4 qo;
        qo.x = aw * bw - ax * bx - ay * by - az * bz;
        qo.y = aw * bx + ax * bw + ay * bz - az * by;
        qo.z = aw * by - ax * bz + ay * bw + az * bx;
        qo.w = aw * bz + ax * by - ay * bx + az * bw;

        out_means[i * 3 + 0] = am0;
        out_means[i * 3 + 1] = am1;
        out_means[i * 3 + 2] = am2;
        reinterpret_cast<float4*>(out_quats)[i] = qo;
    }
}

extern "C" void kernel_launch(void* const* d_in, const int* in_sizes, int n_in,
                              void* d_out, int out_size)
{
    const float* means      = (const float*)d_in[0];
    const float* quats      = (const float*)d_in[1];
    const float* weights    = (const float*)d_in[2];
    const float* ctrl_trans = (const float*)d_in[3];
    const float* ctrl_rots  = (const float*)d_in[4];
    const float* ctrl_pos   = (const float*)d_in[5];
    const int*   indices    = (const int*)d_in[6];

    int n = in_sizes[0] / 3;  // means is [N,3]

    float* out_means = (float*)d_out;
    float* out_quats = (float*)d_out + (size_t)n * 3;

    int max_blocks = NUM_SMS * BLKS_PER_SM;
    int need = (n + TPB - 1) / TPB;
    int blocks = need < max_blocks ? need : max_blocks;

    deform4d_kernel<<<blocks, TPB>>>(means, quats, weights,
                                     ctrl_trans, ctrl_rots, ctrl_pos,
                                     indices, out_means, out_quats, n);
}